// round 15
// baseline (speedup 1.0000x reference)
#include <cuda_runtime.h>
#include <math.h>

#define SEQ   512
#define BATCH 64
#define EMB   300
#define HID   512
#define GATES 2048   // 4*HID
#define NTAG  12
#define NEGV  (-10000.0f)
#define START_TAG 10
#define STOP_TAG  11

// ---------------- scratch (device globals; no allocation) ----------------
__device__ float g_xw[2][SEQ][GATES][BATCH];   // pre-activations x@W_ih.T+b
__device__ __align__(256) float g_hf[SEQ][HID][BATCH];   // forward hidden states
__device__ __align__(256) float g_hb[SEQ][HID][BATCH];   // backward hidden (scan order)
__device__ __align__(256) float g_hinit[2][HID][BATCH];  // transposed h0
__device__ float g_Wt_ih[2][EMB][GATES];       // W_ih transposed [e][j]
__device__ float g_Wout_t[2 * HID][NTAG];      // W_out transposed [k][t]
__device__ float g_feats[SEQ][BATCH][NTAG];
__device__ float g_crf_part[8];
__device__ unsigned g_cnt4[4];                 // per-chain root counters
__device__ unsigned g_sub4[4][4];              // per-chain sub counters (2-level tree)
__device__ unsigned g_gen4[4];

// ---------------- f32x2 helpers ----------------
__device__ __forceinline__ unsigned long long splat2(float x) {
    unsigned long long r; unsigned u = __float_as_uint(x);
    asm("mov.b64 %0, {%1, %1};" : "=l"(r) : "r"(u));
    return r;
}
__device__ __forceinline__ void ffma2(unsigned long long& d,
                                      unsigned long long a,
                                      unsigned long long b) {
    asm("fma.rn.f32x2 %0, %1, %2, %0;" : "+l"(d) : "l"(a), "l"(b));
}
__device__ __forceinline__ unsigned long long addf2(unsigned long long a,
                                                    unsigned long long b) {
    unsigned long long r;
    asm("add.rn.f32x2 %0, %1, %2;" : "=l"(r) : "l"(a), "l"(b));
    return r;
}
__device__ __forceinline__ float2 unpack2(unsigned long long v) {
    unsigned lo, hi;
    asm("mov.b64 {%0, %1}, %2;" : "=r"(lo), "=r"(hi) : "l"(v));
    float2 f; f.x = __uint_as_float(lo); f.y = __uint_as_float(hi);
    return f;
}
__device__ __forceinline__ float sigf(float x) { return 1.f / (1.f + __expf(-x)); }
__device__ __forceinline__ float tanhfast(float x) { return 2.f / (1.f + __expf(-2.f * x)) - 1.f; }

__device__ __forceinline__ unsigned ld_acq(const unsigned* p) {
    unsigned v;
    asm volatile("ld.acquire.gpu.global.u32 %0, [%1];" : "=r"(v) : "l"(p) : "memory");
    return v;
}
__device__ __forceinline__ unsigned atom_inc(unsigned* p) {
    unsigned v;
    asm volatile("atom.acq_rel.gpu.global.add.u32 %0, [%1], 1;"
                 : "=r"(v) : "l"(p) : "memory");
    return v;
}

// ---------------- prep: transposes + state init + barrier reset ----------------
__global__ void prep_kernel(const float* Wif, const float* Wib, const float* h0,
                            const float* Wout) {
    if (blockIdx.x == 0 && threadIdx.x < 4) {
        g_cnt4[threadIdx.x] = 0;
        g_gen4[threadIdx.x] = 0;
        for (int i = 0; i < 4; i++) g_sub4[threadIdx.x][i] = 0;
    }
    const int N_IH = 2 * EMB * GATES;
    const int N_H  = 2 * HID * BATCH;
    const int N_WO = NTAG * 2 * HID;
    const int total = N_IH + N_H + N_WO;
    for (int idx = blockIdx.x * blockDim.x + threadIdx.x; idx < total;
         idx += gridDim.x * blockDim.x) {
        int i = idx;
        if (i < N_IH) {
            int d = i / (EMB * GATES);
            int r = i % (EMB * GATES);
            int e = r / GATES, j = r % GATES;
            const float* W = d ? Wib : Wif;
            g_Wt_ih[d][e][j] = W[j * EMB + e];
        } else if ((i -= N_IH) < N_H) {
            int d = i / (HID * BATCH);
            int r = i % (HID * BATCH);
            int u = r / BATCH, b = r % BATCH;
            g_hinit[d][u][b] = h0[(d * BATCH + b) * HID + u];
        } else {
            i -= N_H;
            int k = i / NTAG, t = i % NTAG;
            g_Wout_t[k][t] = Wout[t * (2 * HID) + k];
        }
    }
}

// ---------------- input GEMM (f32x2) ----------------
__global__ __launch_bounds__(256)
void xw_gemm(const int* __restrict__ tokens,
             const float* __restrict__ W_emb,
             const float* __restrict__ b_f,
             const float* __restrict__ b_b) {
    int dir = blockIdx.z;
    int s   = blockIdx.y;
    int n0  = blockIdx.x * 128;
    __shared__ float As[16][64];
    __shared__ float Bs[16][128];
    __shared__ int   tokS[64];
    int tid = threadIdx.x;
    if (tid < 64) {
        int srow = dir ? (SEQ - 1 - s) : s;
        tokS[tid] = tokens[tid * SEQ + srow];
    }
    __syncthreads();
    int c0 = (tid >> 3) * 4;
    int b0 = (tid & 7) * 8;
    unsigned long long acc[4][4] = {};
    for (int k0 = 0; k0 < 304; k0 += 16) {
        {
            int b = tid & 63, kk4 = (tid >> 6) * 4;
            int k = k0 + kk4;
            float4 v = {0.f, 0.f, 0.f, 0.f};
            if (k + 3 < EMB)
                v = *(const float4*)(W_emb + (size_t)tokS[b] * EMB + k);
            As[kk4 + 0][b] = v.x;
            As[kk4 + 1][b] = v.y;
            As[kk4 + 2][b] = v.z;
            As[kk4 + 3][b] = v.w;
        }
#pragma unroll
        for (int r = 0; r < 2; r++) {
            int idx = tid + 256 * r;
            int kk = idx >> 5, cg = idx & 31;
            float4 w = {0.f, 0.f, 0.f, 0.f};
            if (k0 + kk < EMB)
                w = *(const float4*)&g_Wt_ih[dir][k0 + kk][n0 + cg * 4];
            *(float4*)&Bs[kk][cg * 4] = w;
        }
        __syncthreads();
#pragma unroll
        for (int kk = 0; kk < 16; kk++) {
            float4 wv = *(const float4*)&Bs[kk][c0];
            unsigned long long w0 = splat2(wv.x), w1 = splat2(wv.y);
            unsigned long long w2 = splat2(wv.z), w3 = splat2(wv.w);
            ulonglong2 xA = *(const ulonglong2*)&As[kk][b0];
            ulonglong2 xB = *(const ulonglong2*)&As[kk][b0 + 4];
            ffma2(acc[0][0], xA.x, w0); ffma2(acc[0][1], xA.y, w0);
            ffma2(acc[0][2], xB.x, w0); ffma2(acc[0][3], xB.y, w0);
            ffma2(acc[1][0], xA.x, w1); ffma2(acc[1][1], xA.y, w1);
            ffma2(acc[1][2], xB.x, w1); ffma2(acc[1][3], xB.y, w1);
            ffma2(acc[2][0], xA.x, w2); ffma2(acc[2][1], xA.y, w2);
            ffma2(acc[2][2], xB.x, w2); ffma2(acc[2][3], xB.y, w2);
            ffma2(acc[3][0], xA.x, w3); ffma2(acc[3][1], xA.y, w3);
            ffma2(acc[3][2], xB.x, w3); ffma2(acc[3][3], xB.y, w3);
        }
        __syncthreads();
    }
    const float* bias = dir ? b_b : b_f;
#pragma unroll
    for (int cc = 0; cc < 4; cc++) {
        int j = n0 + c0 + cc;
        float bv = bias[j];
        float2 p0 = unpack2(acc[cc][0]), p1 = unpack2(acc[cc][1]);
        float2 p2 = unpack2(acc[cc][2]), p3 = unpack2(acc[cc][3]);
        float4 o0 = {p0.x + bv, p0.y + bv, p1.x + bv, p1.y + bv};
        float4 o1 = {p2.x + bv, p2.y + bv, p3.x + bv, p3.y + bv};
        *(float4*)&g_xw[dir][s][j][b0] = o0;
        *(float4*)&g_xw[dir][s][j][b0 + 4] = o1;
    }
}

// ---------------- persistent fused BiLSTM: 4 chains, tree arrival, park region ----
// 128 blocks x 512 thr. Block = (dir, bgroup of 32 batch, 16 units = 64 cols).
// Thread = (kg 0/1, cp 0..31, bq 0..7): 2 cols x 4 batch x 256 k.
#define SWS 513
#define SW_F   (32 * SWS * 2)          // 32832 floats (W pairs)
#define SH_F   (HID * 32)              // 16384 floats (h slab)
#define PARK_F 2048                    // 8 KB park region (256 x 4 u64)
__global__ __launch_bounds__(512, 1)
void lstm_persistent(const float* __restrict__ Whf, const float* __restrict__ Whb,
                     const float* __restrict__ c0in) {
    extern __shared__ float smem[];
    float2* sW = (float2*)smem;               // [32 cp][SWS] float2
    float*  sH = smem + SW_F;                 // h slab: 512 k x 32 b
    unsigned long long* sPark = (unsigned long long*)(smem + SW_F + SH_F);

    int tid = threadIdx.x;
    int bid = blockIdx.x;
    int dir = bid >> 6;
    int bg  = (bid >> 5) & 1;                 // batch group 0/1 (32 batch each)
    int u0  = (bid & 31) * 16;                // 16 hidden units
    int chain = dir * 2 + bg;
    int sub = bid & 3;                        // sub-counter within chain (8 blocks each)
    const float* Whh = dir ? Whb : Whf;

    // stage W pairs: sW[cp][k] = (W[col 2cp][k], W[col 2cp+1][k])
    for (int l = tid; l < 32 * 512; l += 512) {
        int cp = l >> 9, k = l & 511;
        int ca = cp * 2, cb = ca + 1;
        int ja = (ca >> 4) * HID + u0 + (ca & 15);
        int jb = (cb >> 4) * HID + u0 + (cb & 15);
        float2 v;
        v.x = Whh[ja * HID + k];
        v.y = Whh[jb * HID + k];
        sW[cp * SWS + k] = v;
    }

    int kg  = tid >> 8;                          // k-half 0/1 (256 k each)
    int lo  = tid & 255;
    int cp  = lo >> 3;                           // col-pair 0..31
    int c0i = cp * 2, c1i = c0i + 1;
    int b0  = (lo & 7) * 4;                      // local batch base 0..28
    int gb0 = bg * 32 + b0;                      // global batch base
    int k0  = kg * 256;

    float cst;                                   // 1 cell elem per thread
    {
        int uu = (tid >> 5) & 15, b = tid & 31;
        cst = c0in[(dir * BATCH + bg * 32 + b) * HID + (u0 + uu)];
    }
    __syncthreads();

    const float2* wrow = sW + cp * SWS;
    int j0 = (c0i >> 4) * HID + u0 + (c0i & 15);
    int j1 = (c1i >> 4) * HID + u0 + (c1i & 15);

    for (int s = 0; s < SEQ; s++) {
        const float* hprev = (s == 0) ? &g_hinit[dir][0][0]
                                      : (dir ? &g_hb[s - 1][0][0] : &g_hf[s - 1][0][0]);
        // hoist xw loads for reducer group (kg==0)
        float4 x0, x1;
        if (kg == 0) {
            x0 = *(const float4*)&g_xw[dir][s][j0][gb0];
            x1 = *(const float4*)&g_xw[dir][s][j1][gb0];
        }

        // stage h slab: 512 k x 32 b = 4096 f4; 8 f4/thread
#pragma unroll
        for (int r = 0; r < 8; r++) {
            int m = tid + 512 * r;
            int k = m >> 3, c4 = m & 7;
            float4 v = *(const float4*)(hprev + k * BATCH + bg * 32 + c4 * 4);
            *(float4*)(sH + k * 32 + c4 * 4) = v;
        }
        __syncthreads();

        // compute this k-half: 128 iterations of 2 k
        unsigned long long a00 = 0, a01 = 0, a10 = 0, a11 = 0;
#pragma unroll 8
        for (int kk = k0; kk < k0 + 256; kk += 2) {
            float2 wA = wrow[kk];
            float2 wB = wrow[kk + 1];
            unsigned long long hA0 = *(const unsigned long long*)(sH + kk * 32 + b0);
            unsigned long long hA1 = *(const unsigned long long*)(sH + kk * 32 + b0 + 2);
            unsigned long long hB0 = *(const unsigned long long*)(sH + (kk + 1) * 32 + b0);
            unsigned long long hB1 = *(const unsigned long long*)(sH + (kk + 1) * 32 + b0 + 2);
            unsigned long long wa0 = splat2(wA.x), wa1 = splat2(wA.y);
            unsigned long long wb0 = splat2(wB.x), wb1 = splat2(wB.y);
            ffma2(a00, hA0, wa0); ffma2(a01, hA1, wa0);
            ffma2(a10, hA0, wa1); ffma2(a11, hA1, wa1);
            ffma2(a00, hB0, wb0); ffma2(a01, hB1, wb0);
            ffma2(a10, hB0, wb1); ffma2(a11, hB1, wb1);
        }

        // kg1 parks into the DEDICATED park region (no pre-sync needed)
        if (kg == 1) {
            ulonglong2* pp = (ulonglong2*)(sPark + (size_t)lo * 4);
            pp[0] = make_ulonglong2(a00, a01);
            pp[1] = make_ulonglong2(a10, a11);
        }
        __syncthreads();    // parks visible; all sH reads complete

        float* sG = sH;                           // gates region (sH dead until next stage)
        if (kg == 0) {
            const ulonglong2* pp = (const ulonglong2*)(sPark + (size_t)lo * 4);
            ulonglong2 v0 = pp[0], v1 = pp[1];
            a00 = addf2(a00, v0.x); a01 = addf2(a01, v0.y);
            a10 = addf2(a10, v1.x); a11 = addf2(a11, v1.y);
            float2 p0 = unpack2(a00), p1 = unpack2(a01);
            float2 q0 = unpack2(a10), q1 = unpack2(a11);
            float4 o0 = {p0.x + x0.x, p0.y + x0.y, p1.x + x0.z, p1.y + x0.w};
            float4 o1 = {q0.x + x1.x, q0.y + x1.y, q1.x + x1.z, q1.y + x1.w};
            *(float4*)(sG + c0i * 36 + b0) = o0;
            *(float4*)(sG + c1i * 36 + b0) = o1;
        }
        __syncthreads();

        // pointwise: 1 elem/thread (16 units x 32 batch); c in registers
        float* hout = dir ? &g_hb[s][0][0] : &g_hf[s][0][0];
        {
            int uu = (tid >> 5) & 15, b = tid & 31;
            float gi = sG[(0 + uu) * 36 + b];
            float gf = sG[(16 + uu) * 36 + b];
            float gg = sG[(32 + uu) * 36 + b];
            float go = sG[(48 + uu) * 36 + b];
            float iv = sigf(gi), fv = sigf(gf), ov = sigf(go);
            float c = fv * cst + iv * tanhfast(gg);
            cst = c;
            hout[(u0 + uu) * BATCH + bg * 32 + b] = ov * tanhfast(c);
        }
        __syncthreads();

        // 2-level per-chain barrier (8x4 tree arrival), skipped after last step
        if (s < SEQ - 1) {
            if (tid == 0) {
                unsigned target = (unsigned)(s + 1);
                unsigned p = atom_inc(&g_sub4[chain][sub]);
                if (p == 7) {
                    asm volatile("st.relaxed.gpu.global.u32 [%0], %1;"
                                 :: "l"(&g_sub4[chain][sub]), "r"(0u) : "memory");
                    unsigned q = atom_inc(&g_cnt4[chain]);
                    if (q == 3) {
                        asm volatile("st.relaxed.gpu.global.u32 [%0], %1;"
                                     :: "l"(&g_cnt4[chain]), "r"(0u) : "memory");
                        asm volatile("st.release.gpu.global.u32 [%0], %1;"
                                     :: "l"(&g_gen4[chain]), "r"(target) : "memory");
                    }
                }
                unsigned g;
                do { g = ld_acq(&g_gen4[chain]); } while (g < target);
            }
            __syncthreads();
        }
    }
}

// ---------------- feats: K-split, 12 independent chains per thread ----------------
__global__ __launch_bounds__(256)
void feats_kernel(const float* __restrict__ b_out) {
    int s = blockIdx.x;
    int tid = threadIdx.x;
    int b = tid & 63;
    int slice = tid >> 6;
    __shared__ float sred[256][NTAG];
    float a[NTAG];
#pragma unroll
    for (int t = 0; t < NTAG; t++) a[t] = 0.f;

    int base = slice * 256;
    const float* hbase = (base < HID) ? &g_hf[s][base][0]
                                      : &g_hb[SEQ - 1 - s][base - HID][0];
#pragma unroll 4
    for (int k = 0; k < 256; k++) {
        float h = hbase[k * BATCH + b];
        int kg = base + k;
        float4 w0 = *(const float4*)&g_Wout_t[kg][0];
        float4 w1 = *(const float4*)&g_Wout_t[kg][4];
        float4 w2 = *(const float4*)&g_Wout_t[kg][8];
        a[0] += h * w0.x;  a[1] += h * w0.y;  a[2]  += h * w0.z;  a[3]  += h * w0.w;
        a[4] += h * w1.x;  a[5] += h * w1.y;  a[6]  += h * w1.z;  a[7]  += h * w1.w;
        a[8] += h * w2.x;  a[9] += h * w2.y;  a[10] += h * w2.z;  a[11] += h * w2.w;
    }
#pragma unroll
    for (int t = 0; t < NTAG; t++) sred[tid][t] = a[t];
    __syncthreads();
    if (tid < 64) {
#pragma unroll
        for (int t = 0; t < NTAG; t++) {
            float v = b_out[t] + sred[tid][t] + sred[64 + tid][t]
                    + sred[128 + tid][t] + sred[192 + tid][t];
            g_feats[s][tid][t] = v;
        }
    }
}

// ---------------- CRF forward: 8 blocks x 8 batches, feats prefetch ----------------
__global__ __launch_bounds__(96)
void crf_kernel(const int* __restrict__ lengths,
                const float* __restrict__ trans) {
    __shared__ float alpha[8][NTAG];
    __shared__ float tr[NTAG][NTAG];
    __shared__ float termS[8][NTAG];
    int tid = threadIdx.x;
    int b = tid / NTAG, t = tid % NTAG;
    int bg = blockIdx.x * 8 + b;
    for (int l = tid; l < NTAG * NTAG; l += 96)
        tr[l / NTAG][l % NTAG] = trans[l];
    alpha[b][t] = (t == START_TAG) ? 0.f : NEGV;
    int len = lengths[bg];
    __syncthreads();
    float fcur = g_feats[0][bg][t];
    for (int s = 0; s < SEQ; s++) {
        float fnext = (s + 1 < SEQ) ? g_feats[s + 1][bg][t] : 0.f;
        float v[NTAG];
        float mx = -1e30f;
#pragma unroll
        for (int p = 0; p < NTAG; p++) {
            v[p] = alpha[b][p] + tr[t][p];
            mx = fmaxf(mx, v[p]);
        }
        float sum = 0.f;
#pragma unroll
        for (int p = 0; p < NTAG; p++) sum += __expf(v[p] - mx);
        float newv = mx + __logf(sum) + fcur;
        float keep = alpha[b][t];
        float nv = (s < len) ? newv : keep;
        __syncthreads();
        alpha[b][t] = nv;
        __syncthreads();
        fcur = fnext;
    }
    termS[b][t] = alpha[b][t] + tr[STOP_TAG][t];
    __syncthreads();
    if (t == 0) {
        float mx = -1e30f;
#pragma unroll
        for (int p = 0; p < NTAG; p++) mx = fmaxf(mx, termS[b][p]);
        float sum = 0.f;
#pragma unroll
        for (int p = 0; p < NTAG; p++) sum += __expf(termS[b][p] - mx);
        termS[b][0] = mx + __logf(sum);
    }
    __syncthreads();
    if (tid == 0) {
        float s2 = 0.f;
        for (int i = 0; i < 8; i++) s2 += termS[i][0];
        g_crf_part[blockIdx.x] = s2;
    }
}

__global__ void crf_finish(float* __restrict__ out) {
    float s = 0.f;
    for (int i = 0; i < 8; i++) s += g_crf_part[i];
    out[0] = s / (float)BATCH;
}

// ---------------- launch ----------------
extern "C" void kernel_launch(void* const* d_in, const int* in_sizes, int n_in,
                              void* d_out, int out_size) {
    const int*   tokens  = (const int*)  d_in[0];
    const int*   lengths = (const int*)  d_in[1];
    const float* W_emb   = (const float*)d_in[2];
    const float* W_ih_f  = (const float*)d_in[3];
    const float* W_hh_f  = (const float*)d_in[4];
    const float* b_f     = (const float*)d_in[5];
    const float* W_ih_b  = (const float*)d_in[6];
    const float* W_hh_b  = (const float*)d_in[7];
    const float* b_b     = (const float*)d_in[8];
    const float* h0      = (const float*)d_in[9];
    const float* c0      = (const float*)d_in[10];
    const float* W_out   = (const float*)d_in[11];
    const float* b_out   = (const float*)d_in[12];
    const float* trans   = (const float*)d_in[13];
    float* out = (float*)d_out;

    const int SMEM_LSTM = (SW_F + SH_F + PARK_F) * 4;   // 205,056 B
    cudaFuncSetAttribute(lstm_persistent,
                         cudaFuncAttributeMaxDynamicSharedMemorySize, SMEM_LSTM);

    prep_kernel<<<1024, 256>>>(W_ih_f, W_ih_b, h0, W_out);
    xw_gemm<<<dim3(GATES / 128, SEQ, 2), 256>>>(tokens, W_emb, b_f, b_b);
    lstm_persistent<<<128, 512, SMEM_LSTM>>>(W_hh_f, W_hh_b, c0);
    feats_kernel<<<SEQ, 256>>>(b_out);
    crf_kernel<<<8, 96>>>(lengths, trans);
    crf_finish<<<1, 1>>>(out);
}

// round 16
// speedup vs baseline: 1.0405x; 1.0405x over previous
#include <cuda_runtime.h>
#include <math.h>

#define SEQ   512
#define BATCH 64
#define EMB   300
#define HID   512
#define GATES 2048   // 4*HID
#define NTAG  12
#define NEGV  (-10000.0f)
#define START_TAG 10
#define STOP_TAG  11

// ---------------- scratch (device globals; no allocation) ----------------
__device__ float g_xw[2][SEQ][GATES][BATCH];   // pre-activations x@W_ih.T+b
__device__ __align__(256) float g_hf[SEQ][HID][BATCH];   // forward hidden states
__device__ __align__(256) float g_hb[SEQ][HID][BATCH];   // backward hidden (scan order)
__device__ __align__(256) float g_hinit[2][HID][BATCH];  // transposed h0
__device__ float g_Wt_ih[2][EMB][GATES];       // W_ih transposed [e][j]
__device__ float g_Wout_t[2 * HID][NTAG];      // W_out transposed [k][t]
__device__ float g_feats[SEQ][BATCH][NTAG];
__device__ float g_crf_part[8];
__device__ unsigned g_cnt4[4];                 // per (dir,bgroup) chain counters
__device__ unsigned g_gen4[4];

// ---------------- f32x2 helpers ----------------
__device__ __forceinline__ unsigned long long splat2(float x) {
    unsigned long long r; unsigned u = __float_as_uint(x);
    asm("mov.b64 %0, {%1, %1};" : "=l"(r) : "r"(u));
    return r;
}
__device__ __forceinline__ void ffma2(unsigned long long& d,
                                      unsigned long long a,
                                      unsigned long long b) {
    asm("fma.rn.f32x2 %0, %1, %2, %0;" : "+l"(d) : "l"(a), "l"(b));
}
__device__ __forceinline__ unsigned long long addf2(unsigned long long a,
                                                    unsigned long long b) {
    unsigned long long r;
    asm("add.rn.f32x2 %0, %1, %2;" : "=l"(r) : "l"(a), "l"(b));
    return r;
}
__device__ __forceinline__ float2 unpack2(unsigned long long v) {
    unsigned lo, hi;
    asm("mov.b64 {%0, %1}, %2;" : "=r"(lo), "=r"(hi) : "l"(v));
    float2 f; f.x = __uint_as_float(lo); f.y = __uint_as_float(hi);
    return f;
}
__device__ __forceinline__ float sigf(float x) { return 1.f / (1.f + __expf(-x)); }
__device__ __forceinline__ float tanhfast(float x) { return 2.f / (1.f + __expf(-2.f * x)) - 1.f; }

__device__ __forceinline__ unsigned ld_acq(const unsigned* p) {
    unsigned v;
    asm volatile("ld.acquire.gpu.global.u32 %0, [%1];" : "=r"(v) : "l"(p) : "memory");
    return v;
}

// ---------------- prep: transposes + state init + barrier reset ----------------
__global__ void prep_kernel(const float* Wif, const float* Wib, const float* h0,
                            const float* Wout) {
    if (blockIdx.x == 0 && threadIdx.x < 4) {
        g_cnt4[threadIdx.x] = 0;
        g_gen4[threadIdx.x] = 0;
    }
    const int N_IH = 2 * EMB * GATES;
    const int N_H  = 2 * HID * BATCH;
    const int N_WO = NTAG * 2 * HID;
    const int total = N_IH + N_H + N_WO;
    for (int idx = blockIdx.x * blockDim.x + threadIdx.x; idx < total;
         idx += gridDim.x * blockDim.x) {
        int i = idx;
        if (i < N_IH) {
            int d = i / (EMB * GATES);
            int r = i % (EMB * GATES);
            int e = r / GATES, j = r % GATES;
            const float* W = d ? Wib : Wif;
            g_Wt_ih[d][e][j] = W[j * EMB + e];
        } else if ((i -= N_IH) < N_H) {
            int d = i / (HID * BATCH);
            int r = i % (HID * BATCH);
            int u = r / BATCH, b = r % BATCH;
            g_hinit[d][u][b] = h0[(d * BATCH + b) * HID + u];
        } else {
            i -= N_H;
            int k = i / NTAG, t = i % NTAG;
            g_Wout_t[k][t] = Wout[t * (2 * HID) + k];
        }
    }
}

// ---------------- input GEMM (f32x2) ----------------
__global__ __launch_bounds__(256)
void xw_gemm(const int* __restrict__ tokens,
             const float* __restrict__ W_emb,
             const float* __restrict__ b_f,
             const float* __restrict__ b_b) {
    int dir = blockIdx.z;
    int s   = blockIdx.y;
    int n0  = blockIdx.x * 128;
    __shared__ float As[16][64];
    __shared__ float Bs[16][128];
    __shared__ int   tokS[64];
    int tid = threadIdx.x;
    if (tid < 64) {
        int srow = dir ? (SEQ - 1 - s) : s;
        tokS[tid] = tokens[tid * SEQ + srow];
    }
    __syncthreads();
    int c0 = (tid >> 3) * 4;
    int b0 = (tid & 7) * 8;
    unsigned long long acc[4][4] = {};
    for (int k0 = 0; k0 < 304; k0 += 16) {
        {
            int b = tid & 63, kk4 = (tid >> 6) * 4;
            int k = k0 + kk4;
            float4 v = {0.f, 0.f, 0.f, 0.f};
            if (k + 3 < EMB)
                v = *(const float4*)(W_emb + (size_t)tokS[b] * EMB + k);
            As[kk4 + 0][b] = v.x;
            As[kk4 + 1][b] = v.y;
            As[kk4 + 2][b] = v.z;
            As[kk4 + 3][b] = v.w;
        }
#pragma unroll
        for (int r = 0; r < 2; r++) {
            int idx = tid + 256 * r;
            int kk = idx >> 5, cg = idx & 31;
            float4 w = {0.f, 0.f, 0.f, 0.f};
            if (k0 + kk < EMB)
                w = *(const float4*)&g_Wt_ih[dir][k0 + kk][n0 + cg * 4];
            *(float4*)&Bs[kk][cg * 4] = w;
        }
        __syncthreads();
#pragma unroll
        for (int kk = 0; kk < 16; kk++) {
            float4 wv = *(const float4*)&Bs[kk][c0];
            unsigned long long w0 = splat2(wv.x), w1 = splat2(wv.y);
            unsigned long long w2 = splat2(wv.z), w3 = splat2(wv.w);
            ulonglong2 xA = *(const ulonglong2*)&As[kk][b0];
            ulonglong2 xB = *(const ulonglong2*)&As[kk][b0 + 4];
            ffma2(acc[0][0], xA.x, w0); ffma2(acc[0][1], xA.y, w0);
            ffma2(acc[0][2], xB.x, w0); ffma2(acc[0][3], xB.y, w0);
            ffma2(acc[1][0], xA.x, w1); ffma2(acc[1][1], xA.y, w1);
            ffma2(acc[1][2], xB.x, w1); ffma2(acc[1][3], xB.y, w1);
            ffma2(acc[2][0], xA.x, w2); ffma2(acc[2][1], xA.y, w2);
            ffma2(acc[2][2], xB.x, w2); ffma2(acc[2][3], xB.y, w2);
            ffma2(acc[3][0], xA.x, w3); ffma2(acc[3][1], xA.y, w3);
            ffma2(acc[3][2], xB.x, w3); ffma2(acc[3][3], xB.y, w3);
        }
        __syncthreads();
    }
    const float* bias = dir ? b_b : b_f;
#pragma unroll
    for (int cc = 0; cc < 4; cc++) {
        int j = n0 + c0 + cc;
        float bv = bias[j];
        float2 p0 = unpack2(acc[cc][0]), p1 = unpack2(acc[cc][1]);
        float2 p2 = unpack2(acc[cc][2]), p3 = unpack2(acc[cc][3]);
        float4 o0 = {p0.x + bv, p0.y + bv, p1.x + bv, p1.y + bv};
        float4 o1 = {p2.x + bv, p2.y + bv, p3.x + bv, p3.y + bv};
        *(float4*)&g_xw[dir][s][j][b0] = o0;
        *(float4*)&g_xw[dir][s][j][b0 + 4] = o1;
    }
}

// ---------------- persistent fused BiLSTM: 4 chains (R14) + split finalize ------
// 128 blocks x 512 thr. Block = (dir, bgroup of 32 batch, 16 units = 64 cols).
// Thread = (kg 0/1, cp 0..31, bq 0..7): 2 cols x 4 batch x 256 k.
// Finalizer = (kg0, cp<16) or (kg1, cp>=16); partner parks into dedicated region.
#define SWS 513
#define SW_F   (32 * SWS * 2)          // 32832 floats (W pairs)
#define SH_F   (HID * 32)              // 16384 floats (h slab)
__global__ __launch_bounds__(512, 1)
void lstm_persistent(const float* __restrict__ Whf, const float* __restrict__ Whb,
                     const float* __restrict__ c0in) {
    extern __shared__ float smem[];
    float2* sW = (float2*)smem;               // [32 cp][SWS] float2
    float*  sH = smem + SW_F;                 // h slab: 512 k x 32 b
    unsigned long long* sPark = (unsigned long long*)(smem + SW_F + SH_F); // 512 x 4 u64

    int tid = threadIdx.x;
    int bid = blockIdx.x;
    int dir = bid >> 6;
    int bg  = (bid >> 5) & 1;                 // batch group 0/1 (32 batch each)
    int u0  = (bid & 31) * 16;                // 16 hidden units
    int chain = dir * 2 + bg;
    const float* Whh = dir ? Whb : Whf;

    // stage W pairs: sW[cp][k] = (W[col 2cp][k], W[col 2cp+1][k])
    // col c (0..63): gate = c>>4, unit = c&15
    for (int l = tid; l < 32 * 512; l += 512) {
        int cp = l >> 9, k = l & 511;
        int ca = cp * 2, cb = ca + 1;
        int ja = (ca >> 4) * HID + u0 + (ca & 15);
        int jb = (cb >> 4) * HID + u0 + (cb & 15);
        float2 v;
        v.x = Whh[ja * HID + k];
        v.y = Whh[jb * HID + k];
        sW[cp * SWS + k] = v;
    }

    int kg  = tid >> 8;                          // k-half 0/1 (256 k each)
    int lo  = tid & 255;
    int cp  = lo >> 3;                           // col-pair 0..31
    int c0i = cp * 2, c1i = c0i + 1;
    int b0  = (lo & 7) * 4;                      // local batch base 0..28
    int gb0 = bg * 32 + b0;                      // global batch base
    int k0  = kg * 256;
    bool fin = (kg == 0) ? (cp < 16) : (cp >= 16);   // finalizer role
    int park_self    = kg * 256 + lo;
    int park_partner = (kg ^ 1) * 256 + lo;

    float cst;                                   // 1 cell elem per thread
    {
        int uu = (tid >> 5) & 15, b = tid & 31;
        cst = c0in[(dir * BATCH + bg * 32 + b) * HID + (u0 + uu)];
    }
    __syncthreads();

    const float2* wrow = sW + cp * SWS;
    int j0 = (c0i >> 4) * HID + u0 + (c0i & 15);
    int j1 = (c1i >> 4) * HID + u0 + (c1i & 15);

    for (int s = 0; s < SEQ; s++) {
        const float* hprev = (s == 0) ? &g_hinit[dir][0][0]
                                      : (dir ? &g_hb[s - 1][0][0] : &g_hf[s - 1][0][0]);
        // hoist xw loads for finalizer threads
        float4 x0, x1;
        if (fin) {
            x0 = *(const float4*)&g_xw[dir][s][j0][gb0];
            x1 = *(const float4*)&g_xw[dir][s][j1][gb0];
        }

        // stage h slab: 512 k x 32 b = 4096 f4; 8 f4/thread
#pragma unroll
        for (int r = 0; r < 8; r++) {
            int m = tid + 512 * r;
            int k = m >> 3, c4 = m & 7;
            float4 v = *(const float4*)(hprev + k * BATCH + bg * 32 + c4 * 4);
            *(float4*)(sH + k * 32 + c4 * 4) = v;
        }
        __syncthreads();

        // compute this k-half: 128 iterations of 2 k
        unsigned long long a00 = 0, a01 = 0, a10 = 0, a11 = 0;
#pragma unroll 8
        for (int kk = k0; kk < k0 + 256; kk += 2) {
            float2 wA = wrow[kk];
            float2 wB = wrow[kk + 1];
            unsigned long long hA0 = *(const unsigned long long*)(sH + kk * 32 + b0);
            unsigned long long hA1 = *(const unsigned long long*)(sH + kk * 32 + b0 + 2);
            unsigned long long hB0 = *(const unsigned long long*)(sH + (kk + 1) * 32 + b0);
            unsigned long long hB1 = *(const unsigned long long*)(sH + (kk + 1) * 32 + b0 + 2);
            unsigned long long wa0 = splat2(wA.x), wa1 = splat2(wA.y);
            unsigned long long wb0 = splat2(wB.x), wb1 = splat2(wB.y);
            ffma2(a00, hA0, wa0); ffma2(a01, hA1, wa0);
            ffma2(a10, hA0, wa1); ffma2(a11, hA1, wa1);
            ffma2(a00, hB0, wb0); ffma2(a01, hB1, wb0);
            ffma2(a10, hB0, wb1); ffma2(a11, hB1, wb1);
        }

        // non-finalizers park into the dedicated region (no pre-sync needed)
        if (!fin) {
            ulonglong2* pp = (ulonglong2*)(sPark + (size_t)park_self * 4);
            pp[0] = make_ulonglong2(a00, a01);
            pp[1] = make_ulonglong2(a10, a11);
        }
        __syncthreads();    // parks visible; all sH reads complete

        float* sG = sH;     // gates region reuses dead sH
        if (fin) {
            const ulonglong2* pp = (const ulonglong2*)(sPark + (size_t)park_partner * 4);
            ulonglong2 v0 = pp[0], v1 = pp[1];
            a00 = addf2(a00, v0.x); a01 = addf2(a01, v0.y);
            a10 = addf2(a10, v1.x); a11 = addf2(a11, v1.y);
            float2 p0 = unpack2(a00), p1 = unpack2(a01);
            float2 q0 = unpack2(a10), q1 = unpack2(a11);
            float4 o0 = {p0.x + x0.x, p0.y + x0.y, p1.x + x0.z, p1.y + x0.w};
            float4 o1 = {q0.x + x1.x, q0.y + x1.y, q1.x + x1.z, q1.y + x1.w};
            *(float4*)(sG + c0i * 36 + b0) = o0;
            *(float4*)(sG + c1i * 36 + b0) = o1;
        }
        __syncthreads();

        // pointwise: 1 elem/thread (16 units x 32 batch); c in registers
        float* hout = dir ? &g_hb[s][0][0] : &g_hf[s][0][0];
        {
            int uu = (tid >> 5) & 15, b = tid & 31;
            float gi = sG[(0 + uu) * 36 + b];
            float gf = sG[(16 + uu) * 36 + b];
            float gg = sG[(32 + uu) * 36 + b];
            float go = sG[(48 + uu) * 36 + b];
            float iv = sigf(gi), fv = sigf(gf), ov = sigf(go);
            float c = fv * cst + iv * tanhfast(gg);
            cst = c;
            hout[(u0 + uu) * BATCH + bg * 32 + b] = ov * tanhfast(c);
        }
        __syncthreads();

        // per-chain grid barrier (flat 32 arrivals), skipped after last step
        if (s < SEQ - 1) {
            if (tid == 0) {
                unsigned target = (unsigned)(s + 1);
                unsigned prev;
                asm volatile("atom.acq_rel.gpu.global.add.u32 %0, [%1], 1;"
                             : "=r"(prev) : "l"(&g_cnt4[chain]) : "memory");
                if (prev == 31) {
                    asm volatile("st.relaxed.gpu.global.u32 [%0], %1;"
                                 :: "l"(&g_cnt4[chain]), "r"(0u) : "memory");
                    asm volatile("st.release.gpu.global.u32 [%0], %1;"
                                 :: "l"(&g_gen4[chain]), "r"(target) : "memory");
                } else {
                    unsigned g;
                    do { g = ld_acq(&g_gen4[chain]); } while (g < target);
                }
            }
            __syncthreads();
        }
    }
}

// ---------------- feats: K-split, 12 independent chains per thread ----------------
__global__ __launch_bounds__(256)
void feats_kernel(const float* __restrict__ b_out) {
    int s = blockIdx.x;
    int tid = threadIdx.x;
    int b = tid & 63;
    int slice = tid >> 6;
    __shared__ float sred[256][NTAG];
    float a[NTAG];
#pragma unroll
    for (int t = 0; t < NTAG; t++) a[t] = 0.f;

    int base = slice * 256;
    const float* hbase = (base < HID) ? &g_hf[s][base][0]
                                      : &g_hb[SEQ - 1 - s][base - HID][0];
#pragma unroll 4
    for (int k = 0; k < 256; k++) {
        float h = hbase[k * BATCH + b];
        int kg = base + k;
        float4 w0 = *(const float4*)&g_Wout_t[kg][0];
        float4 w1 = *(const float4*)&g_Wout_t[kg][4];
        float4 w2 = *(const float4*)&g_Wout_t[kg][8];
        a[0] += h * w0.x;  a[1] += h * w0.y;  a[2]  += h * w0.z;  a[3]  += h * w0.w;
        a[4] += h * w1.x;  a[5] += h * w1.y;  a[6]  += h * w1.z;  a[7]  += h * w1.w;
        a[8] += h * w2.x;  a[9] += h * w2.y;  a[10] += h * w2.z;  a[11] += h * w2.w;
    }
#pragma unroll
    for (int t = 0; t < NTAG; t++) sred[tid][t] = a[t];
    __syncthreads();
    if (tid < 64) {
#pragma unroll
        for (int t = 0; t < NTAG; t++) {
            float v = b_out[t] + sred[tid][t] + sred[64 + tid][t]
                    + sred[128 + tid][t] + sred[192 + tid][t];
            g_feats[s][tid][t] = v;
        }
    }
}

// ---------------- CRF forward: 8 blocks x 8 batches, feats prefetch ----------------
__global__ __launch_bounds__(96)
void crf_kernel(const int* __restrict__ lengths,
                const float* __restrict__ trans) {
    __shared__ float alpha[8][NTAG];
    __shared__ float tr[NTAG][NTAG];
    __shared__ float termS[8][NTAG];
    int tid = threadIdx.x;
    int b = tid / NTAG, t = tid % NTAG;
    int bg = blockIdx.x * 8 + b;
    for (int l = tid; l < NTAG * NTAG; l += 96)
        tr[l / NTAG][l % NTAG] = trans[l];
    alpha[b][t] = (t == START_TAG) ? 0.f : NEGV;
    int len = lengths[bg];
    __syncthreads();
    float fcur = g_feats[0][bg][t];
    for (int s = 0; s < SEQ; s++) {
        float fnext = (s + 1 < SEQ) ? g_feats[s + 1][bg][t] : 0.f;
        float v[NTAG];
        float mx = -1e30f;
#pragma unroll
        for (int p = 0; p < NTAG; p++) {
            v[p] = alpha[b][p] + tr[t][p];
            mx = fmaxf(mx, v[p]);
        }
        float sum = 0.f;
#pragma unroll
        for (int p = 0; p < NTAG; p++) sum += __expf(v[p] - mx);
        float newv = mx + __logf(sum) + fcur;
        float keep = alpha[b][t];
        float nv = (s < len) ? newv : keep;
        __syncthreads();
        alpha[b][t] = nv;
        __syncthreads();
        fcur = fnext;
    }
    termS[b][t] = alpha[b][t] + tr[STOP_TAG][t];
    __syncthreads();
    if (t == 0) {
        float mx = -1e30f;
#pragma unroll
        for (int p = 0; p < NTAG; p++) mx = fmaxf(mx, termS[b][p]);
        float sum = 0.f;
#pragma unroll
        for (int p = 0; p < NTAG; p++) sum += __expf(termS[b][p] - mx);
        termS[b][0] = mx + __logf(sum);
    }
    __syncthreads();
    if (tid == 0) {
        float s2 = 0.f;
        for (int i = 0; i < 8; i++) s2 += termS[i][0];
        g_crf_part[blockIdx.x] = s2;
    }
}

__global__ void crf_finish(float* __restrict__ out) {
    float s = 0.f;
    for (int i = 0; i < 8; i++) s += g_crf_part[i];
    out[0] = s / (float)BATCH;
}

// ---------------- launch ----------------
extern "C" void kernel_launch(void* const* d_in, const int* in_sizes, int n_in,
                              void* d_out, int out_size) {
    const int*   tokens  = (const int*)  d_in[0];
    const int*   lengths = (const int*)  d_in[1];
    const float* W_emb   = (const float*)d_in[2];
    const float* W_ih_f  = (const float*)d_in[3];
    const float* W_hh_f  = (const float*)d_in[4];
    const float* b_f     = (const float*)d_in[5];
    const float* W_ih_b  = (const float*)d_in[6];
    const float* W_hh_b  = (const float*)d_in[7];
    const float* b_b     = (const float*)d_in[8];
    const float* h0      = (const float*)d_in[9];
    const float* c0      = (const float*)d_in[10];
    const float* W_out   = (const float*)d_in[11];
    const float* b_out   = (const float*)d_in[12];
    const float* trans   = (const float*)d_in[13];
    float* out = (float*)d_out;

    const int SMEM_LSTM = (SW_F + SH_F) * 4 + 512 * 4 * 8;   // 213,248 B
    cudaFuncSetAttribute(lstm_persistent,
                         cudaFuncAttributeMaxDynamicSharedMemorySize, SMEM_LSTM);

    prep_kernel<<<1024, 256>>>(W_ih_f, W_ih_b, h0, W_out);
    xw_gemm<<<dim3(GATES / 128, SEQ, 2), 256>>>(tokens, W_emb, b_f, b_b);
    lstm_persistent<<<128, 512, SMEM_LSTM>>>(W_hh_f, W_hh_b, c0);
    feats_kernel<<<SEQ, 256>>>(b_out);
    crf_kernel<<<8, 96>>>(lengths, trans);
    crf_finish<<<1, 1>>>(out);
}